// round 2
// baseline (speedup 1.0000x reference)
#include <cuda_runtime.h>

#define TT 2048
#define IN 64
#define HH 512
#define G4 2048   /* 4*H */
#define GRID_REC 128
#define THR_REC 256

// ---------------- device scratch (static allocations only) ----------------
__device__ float g_pre[TT * G4];      // pregates for current layer [T, 4H]
__device__ float g_hA[TT * HH];       // layer output ping
__device__ float g_hB[TT * HH];       // layer output pong
__device__ unsigned int g_flags[TT];  // per-step barrier counters

__device__ __forceinline__ float sigmoidf_(float x) {
    return 1.0f / (1.0f + __expf(-x));
}
__device__ __forceinline__ float tanhfast_(float x) {
    return 2.0f / (1.0f + __expf(-2.0f * x)) - 1.0f;
}

// ---------------- GEMM: pre[m][n] = dot(A[m,:], B[n,:]) + b1[n] + b2[n] ----
// A: [T, K] row-major, B: [4H, K] row-major, out: g_pre [T, 4H]
// If Aext != nullptr use it, else use ping/pong buffer selected by asel.
__global__ void __launch_bounds__(256) gemm_pregate(
    const float* __restrict__ Aext, int asel, int K,
    const float* __restrict__ B,
    const float* __restrict__ b1, const float* __restrict__ b2)
{
    __shared__ float As[16][129];
    __shared__ float Bs[16][129];

    const float* A = Aext ? Aext : (asel ? g_hB : g_hA);

    int tid = threadIdx.x;
    int m0 = blockIdx.y * 128;
    int n0 = blockIdx.x * 128;
    int row = tid >> 1;
    int kh  = (tid & 1) * 8;
    int tx = tid & 15, ty = tid >> 4;

    float acc[8][8];
#pragma unroll
    for (int i = 0; i < 8; i++)
#pragma unroll
        for (int j = 0; j < 8; j++) acc[i][j] = 0.0f;

    for (int kt = 0; kt < K; kt += 16) {
        float4 a0 = *(const float4*)(A + (size_t)(m0 + row) * K + kt + kh);
        float4 a1 = *(const float4*)(A + (size_t)(m0 + row) * K + kt + kh + 4);
        float4 c0 = *(const float4*)(B + (size_t)(n0 + row) * K + kt + kh);
        float4 c1 = *(const float4*)(B + (size_t)(n0 + row) * K + kt + kh + 4);
        __syncthreads();
        As[kh + 0][row] = a0.x; As[kh + 1][row] = a0.y;
        As[kh + 2][row] = a0.z; As[kh + 3][row] = a0.w;
        As[kh + 4][row] = a1.x; As[kh + 5][row] = a1.y;
        As[kh + 6][row] = a1.z; As[kh + 7][row] = a1.w;
        Bs[kh + 0][row] = c0.x; Bs[kh + 1][row] = c0.y;
        Bs[kh + 2][row] = c0.z; Bs[kh + 3][row] = c0.w;
        Bs[kh + 4][row] = c1.x; Bs[kh + 5][row] = c1.y;
        Bs[kh + 6][row] = c1.z; Bs[kh + 7][row] = c1.w;
        __syncthreads();
#pragma unroll
        for (int k = 0; k < 16; k++) {
            float a[8], b[8];
#pragma unroll
            for (int i = 0; i < 8; i++) a[i] = As[k][ty * 8 + i];
#pragma unroll
            for (int j = 0; j < 8; j++) b[j] = Bs[k][tx * 8 + j];
#pragma unroll
            for (int i = 0; i < 8; i++)
#pragma unroll
                for (int j = 0; j < 8; j++)
                    acc[i][j] = fmaf(a[i], b[j], acc[i][j]);
        }
    }

#pragma unroll
    for (int i = 0; i < 8; i++) {
        int m = m0 + ty * 8 + i;
#pragma unroll
        for (int j = 0; j < 8; j++) {
            int n = n0 + tx * 8 + j;
            g_pre[(size_t)m * G4 + n] = acc[i][j] + b1[n] + b2[n];
        }
    }
}

// ---------------- zero the per-step barrier flags ----------------
__global__ void zero_flags() {
    g_flags[blockIdx.x * 256 + threadIdx.x] = 0u;
}

// ---------------- persistent LSTM recurrence for one layer ----------------
// gates[t] = g_pre[t] + w_hh @ h_{t-1}; output written to ping/pong by osel.
// CTA b owns h indices [4b, 4b+4). Warp w handles gate rows (g0, g0+1) of
// h sub-index jj = w>>1, g0 = (w&1)*2.  Row (g,j) = g*512 + j.
// Weights live in registers (32 floats/thread). Global spin barrier per step.
__global__ void __launch_bounds__(THR_REC) lstm_rec(
    const float* __restrict__ whh, int osel)
{
    __shared__ float hsh[HH];
    __shared__ float gsh[16];
    __shared__ float csm[4];

    float* hout = osel ? g_hB : g_hA;

    int tid  = threadIdx.x;
    int w    = tid >> 5;
    int lane = tid & 31;
    int jj   = w >> 1;
    int g0   = (w & 1) * 2;
    int j    = blockIdx.x * 4 + jj;
    int row0 = g0 * HH + j;
    int row1 = (g0 + 1) * HH + j;

    float w0[16], w1[16];
#pragma unroll
    for (int k = 0; k < 16; k++) {
        w0[k] = whh[(size_t)row0 * HH + lane + 32 * k];
        w1[k] = whh[(size_t)row1 * HH + lane + 32 * k];
    }

    if (tid < 4) csm[tid] = 0.0f;
    for (int i = tid; i < HH; i += THR_REC) hsh[i] = 0.0f;
    __syncthreads();

#pragma unroll 1
    for (int t = 0; t < TT; t++) {
        // prefetch pregates (independent of h)
        float pre0 = 0.0f, pre1 = 0.0f;
        if (lane == 0) {
            pre0 = g_pre[(size_t)t * G4 + row0];
            pre1 = g_pre[(size_t)t * G4 + row1];
        }

        // mat-vec partials: conflict-free LDS, register weights
        float a0 = 0.f, b0 = 0.f, a1 = 0.f, b1 = 0.f;
#pragma unroll
        for (int k = 0; k < 16; k += 2) {
            float h0 = hsh[lane + 32 * k];
            float h1 = hsh[lane + 32 * (k + 1)];
            a0 = fmaf(w0[k],     h0, a0);
            a1 = fmaf(w1[k],     h0, a1);
            b0 = fmaf(w0[k + 1], h1, b0);
            b1 = fmaf(w1[k + 1], h1, b1);
        }
        float acc0 = a0 + b0, acc1 = a1 + b1;
#pragma unroll
        for (int off = 16; off; off >>= 1) {
            acc0 += __shfl_xor_sync(0xffffffffu, acc0, off);
            acc1 += __shfl_xor_sync(0xffffffffu, acc1, off);
        }
        if (lane == 0) {
            gsh[jj * 4 + g0]     = acc0 + pre0;
            gsh[jj * 4 + g0 + 1] = acc1 + pre1;
        }
        __syncthreads();

        // gate math + state update + h write (4 threads, one per h index)
        if (tid < 4) {
            float gi = sigmoidf_(gsh[tid * 4 + 0]);
            float gf = sigmoidf_(gsh[tid * 4 + 1]);
            float gg = tanhfast_(gsh[tid * 4 + 2]);
            float go = sigmoidf_(gsh[tid * 4 + 3]);
            float c  = fmaf(gf, csm[tid], gi * gg);
            csm[tid] = c;
            hout[(size_t)t * HH + blockIdx.x * 4 + tid] = go * tanhfast_(c);
        }
        __syncthreads();

        // global barrier: release stores, arrive, poll
        if (tid == 0) {
            __threadfence();
            atomicAdd(&g_flags[t], 1u);
            unsigned v;
            do {
                asm volatile("ld.acquire.gpu.global.u32 %0, [%1];"
                             : "=r"(v) : "l"(&g_flags[t]) : "memory");
            } while (v < (unsigned)GRID_REC);
        }
        __syncthreads();

        // stage h_t for next step (bypass L1 — written by other SMs)
        {
            const float2* src = (const float2*)(hout + (size_t)t * HH);
            float2 v2 = __ldcg(src + tid);
            hsh[tid * 2]     = v2.x;
            hsh[tid * 2 + 1] = v2.y;
        }
        __syncthreads();
    }
}

// ---------------- finalize: attention-weighted mean ----------------
__global__ void __launch_bounds__(1024) finalize(
    int sel, const float* __restrict__ wlin, const float* __restrict__ blin,
    float* __restrict__ out)
{
    __shared__ float wl[HH];
    __shared__ float av[TT];
    __shared__ float red[32];
    __shared__ float stats[2];

    const float* hin = sel ? g_hB : g_hA;
    int tid = threadIdx.x, w = tid >> 5, lane = tid & 31;

    for (int i = tid; i < HH; i += 1024) wl[i] = wlin[i];
    __syncthreads();
    float bl = blin[0];

    // e[t] = h[t]·wlin + b ; av[t] = tanh(e[t])
    for (int r = w; r < TT; r += 32) {
        float acc = 0.0f;
#pragma unroll
        for (int k = 0; k < 16; k++)
            acc = fmaf(hin[(size_t)r * HH + lane + 32 * k], wl[lane + 32 * k], acc);
#pragma unroll
        for (int off = 16; off; off >>= 1)
            acc += __shfl_xor_sync(0xffffffffu, acc, off);
        if (lane == 0) av[r] = tanhfast_(acc + bl);
    }
    __syncthreads();

    // softmax over time: max
    float m = -1e30f;
    for (int i = tid; i < TT; i += 1024) m = fmaxf(m, av[i]);
#pragma unroll
    for (int off = 16; off; off >>= 1)
        m = fmaxf(m, __shfl_xor_sync(0xffffffffu, m, off));
    if (lane == 0) red[w] = m;
    __syncthreads();
    if (w == 0) {
        float mm = red[lane];
#pragma unroll
        for (int off = 16; off; off >>= 1)
            mm = fmaxf(mm, __shfl_xor_sync(0xffffffffu, mm, off));
        if (lane == 0) stats[0] = mm;
    }
    __syncthreads();
    float bmax = stats[0];

    // exp + sum
    float s = 0.0f;
    for (int i = tid; i < TT; i += 1024) {
        float e = __expf(av[i] - bmax);
        av[i] = e;
        s += e;
    }
#pragma unroll
    for (int off = 16; off; off >>= 1)
        s += __shfl_xor_sync(0xffffffffu, s, off);
    if (lane == 0) red[w] = s;
    __syncthreads();
    if (w == 0) {
        float ss = red[lane];
#pragma unroll
        for (int off = 16; off; off >>= 1)
            ss += __shfl_xor_sync(0xffffffffu, ss, off);
        if (lane == 0) stats[1] = ss;
    }
    __syncthreads();
    float inv = 1.0f / (stats[1] * (float)TT);

    // out[j] = (1/T) * sum_t softmax_t * h[t][j]
    int jcol = tid & (HH - 1);
    int half = tid >> 9;
    float acc = 0.0f;
    int t0 = half * (TT / 2);
    for (int t = t0; t < t0 + TT / 2; t++)
        acc = fmaf(av[t], hin[(size_t)t * HH + jcol], acc);
    __syncthreads();   // wl no longer needed; reuse as partial buffer
    if (half == 0) wl[jcol] = acc;
    __syncthreads();
    if (half == 1) out[jcol] = (wl[jcol] + acc) * inv;
}

// ---------------- host: launch sequence (graph-capturable) ----------------
extern "C" void kernel_launch(void* const* d_in, const int* in_sizes, int n_in,
                              void* d_out, int out_size)
{
    const float* x     = (const float*)d_in[0];
    const float* w_ih0 = (const float*)d_in[1];
    const float* w_hh0 = (const float*)d_in[2];
    const float* b_ih0 = (const float*)d_in[3];
    const float* b_hh0 = (const float*)d_in[4];
    const float* w_ih  = (const float*)d_in[5];
    const float* w_hh  = (const float*)d_in[6];
    const float* b_ih  = (const float*)d_in[7];
    const float* b_hh  = (const float*)d_in[8];
    const float* w_lin = (const float*)d_in[9];
    const float* b_lin = (const float*)d_in[10];
    float* out = (float*)d_out;

    dim3 gg(G4 / 128, TT / 128);

    // layer 0 (input dim 64)
    gemm_pregate<<<gg, 256>>>(x, 0, IN, w_ih0, b_ih0, b_hh0);
    zero_flags<<<TT / 256, 256>>>();
    lstm_rec<<<GRID_REC, THR_REC>>>(w_hh0, 0);   // writes g_hA

    int cur = 0;  // 0 -> g_hA holds current layer output
    for (int l = 0; l < 4; l++) {
        gemm_pregate<<<gg, 256>>>(nullptr, cur, HH,
                                  w_ih + (size_t)l * G4 * HH,
                                  b_ih + (size_t)l * G4,
                                  b_hh + (size_t)l * G4);
        zero_flags<<<TT / 256, 256>>>();
        lstm_rec<<<GRID_REC, THR_REC>>>(w_hh + (size_t)l * G4 * HH, cur ^ 1);
        cur ^= 1;
    }

    finalize<<<1, 1024>>>(cur, w_lin, b_lin, out);
}

// round 5
// speedup vs baseline: 1.5612x; 1.5612x over previous
#include <cuda_runtime.h>

#define TT 2048
#define IN 64
#define HH 512
#define G4 2048   /* 4*H */
#define GRID_REC 128
#define THR_REC 256

// ---------------- device scratch (static allocations only) ----------------
__device__ float g_pre[TT * G4];      // pregates for current layer [T, 4H]
__device__ float g_hA[TT * HH];       // layer output ping
__device__ float g_hB[TT * HH];       // layer output pong
// h exchange: one 64-bit word per h index, double buffered on t&1.
// word = (epoch << 32) | float_bits(h). Aligned 8B relaxed atomics are
// single-copy atomic in the PTX memory model -> data+tag indivisible.
__device__ unsigned long long g_slots64[2][HH];

__device__ __forceinline__ float sigmoidf_(float x) {
    return 1.0f / (1.0f + __expf(-x));
}
__device__ __forceinline__ float tanhfast_(float x) {
    return 2.0f / (1.0f + __expf(-2.0f * x)) - 1.0f;
}

// ---------------- GEMM: pre[m][n] = dot(A[m,:], B[n,:]) + b1[n] + b2[n] ----
__global__ void __launch_bounds__(256) gemm_pregate(
    const float* __restrict__ Aext, int asel, int K,
    const float* __restrict__ B,
    const float* __restrict__ b1, const float* __restrict__ b2)
{
    __shared__ float As[16][129];
    __shared__ float Bs[16][129];

    const float* A = Aext ? Aext : (asel ? g_hB : g_hA);

    int tid = threadIdx.x;
    int m0 = blockIdx.y * 128;
    int n0 = blockIdx.x * 128;
    int row = tid >> 1;
    int kh  = (tid & 1) * 8;
    int tx = tid & 15, ty = tid >> 4;

    float acc[8][8];
#pragma unroll
    for (int i = 0; i < 8; i++)
#pragma unroll
        for (int j = 0; j < 8; j++) acc[i][j] = 0.0f;

    for (int kt = 0; kt < K; kt += 16) {
        float4 a0 = *(const float4*)(A + (size_t)(m0 + row) * K + kt + kh);
        float4 a1 = *(const float4*)(A + (size_t)(m0 + row) * K + kt + kh + 4);
        float4 c0 = *(const float4*)(B + (size_t)(n0 + row) * K + kt + kh);
        float4 c1 = *(const float4*)(B + (size_t)(n0 + row) * K + kt + kh + 4);
        __syncthreads();
        As[kh + 0][row] = a0.x; As[kh + 1][row] = a0.y;
        As[kh + 2][row] = a0.z; As[kh + 3][row] = a0.w;
        As[kh + 4][row] = a1.x; As[kh + 5][row] = a1.y;
        As[kh + 6][row] = a1.z; As[kh + 7][row] = a1.w;
        Bs[kh + 0][row] = c0.x; Bs[kh + 1][row] = c0.y;
        Bs[kh + 2][row] = c0.z; Bs[kh + 3][row] = c0.w;
        Bs[kh + 4][row] = c1.x; Bs[kh + 5][row] = c1.y;
        Bs[kh + 6][row] = c1.z; Bs[kh + 7][row] = c1.w;
        __syncthreads();
#pragma unroll
        for (int k = 0; k < 16; k++) {
            float a[8], b[8];
#pragma unroll
            for (int i = 0; i < 8; i++) a[i] = As[k][ty * 8 + i];
#pragma unroll
            for (int j = 0; j < 8; j++) b[j] = Bs[k][tx * 8 + j];
#pragma unroll
            for (int i = 0; i < 8; i++)
#pragma unroll
                for (int j = 0; j < 8; j++)
                    acc[i][j] = fmaf(a[i], b[j], acc[i][j]);
        }
    }

#pragma unroll
    for (int i = 0; i < 8; i++) {
        int m = m0 + ty * 8 + i;
#pragma unroll
        for (int j = 0; j < 8; j++) {
            int n = n0 + tx * 8 + j;
            g_pre[(size_t)m * G4 + n] = acc[i][j] + b1[n] + b2[n];
        }
    }
}

// ---------------- init: zero the slots (once per launch) ----------------
__global__ void init_slots() {
    g_slots64[0][threadIdx.x] = 0ull;
    g_slots64[1][threadIdx.x] = 0ull;
}

// ---------------- persistent LSTM recurrence for one layer ----------------
// CTA b owns h indices [4b, 4b+4). Warp w handles gate rows (g0, g0+1) of
// h sub-index jj = w>>1, g0 = (w&1)*2.  Row (g,j) = g*512 + j.
// Weights in registers (32 floats/thread).
// h exchange via 64-bit relaxed atomics: producer packs {epoch, h} into one
// aligned u64 (single-copy atomic => no tearing, no fence needed); each
// consumer thread polls its two h-slots until the epoch tag matches, then
// drops the payload into SMEM. Wait + data fused into one L2 round trip.
__global__ void __launch_bounds__(THR_REC) lstm_rec(
    const float* __restrict__ whh, int osel, unsigned ebase)
{
    __shared__ float hsh[HH];
    __shared__ float gsh[16];

    float* hout = osel ? g_hB : g_hA;

    int tid  = threadIdx.x;
    int w    = tid >> 5;
    int lane = tid & 31;
    int jj   = w >> 1;
    int g0   = (w & 1) * 2;
    int j    = blockIdx.x * 4 + jj;
    int row0 = g0 * HH + j;
    int row1 = (g0 + 1) * HH + j;

    float w0[16], w1[16];
#pragma unroll
    for (int k = 0; k < 16; k++) {
        w0[k] = whh[(size_t)row0 * HH + lane + 32 * k];
        w1[k] = whh[(size_t)row1 * HH + lane + 32 * k];
    }

    float cstate = 0.0f;   // cell state, live only in threads 0..3
    for (int i = tid; i < HH; i += THR_REC) hsh[i] = 0.0f;

    // prefetch pregates for t=0
    float pre0 = 0.0f, pre1 = 0.0f;
    if (lane == 0) {
        pre0 = g_pre[row0];
        pre1 = g_pre[row1];
    }
    __syncthreads();

#pragma unroll 1
    for (int t = 0; t < TT; t++) {
        // mat-vec partials: conflict-free LDS, register weights
        float a0 = 0.f, b0 = 0.f, a1 = 0.f, b1 = 0.f;
#pragma unroll
        for (int k = 0; k < 16; k += 2) {
            float h0 = hsh[lane + 32 * k];
            float h1 = hsh[lane + 32 * (k + 1)];
            a0 = fmaf(w0[k],     h0, a0);
            a1 = fmaf(w1[k],     h0, a1);
            b0 = fmaf(w0[k + 1], h1, b0);
            b1 = fmaf(w1[k + 1], h1, b1);
        }
        float acc0 = a0 + b0, acc1 = a1 + b1;
#pragma unroll
        for (int off = 16; off; off >>= 1) {
            acc0 += __shfl_xor_sync(0xffffffffu, acc0, off);
            acc1 += __shfl_xor_sync(0xffffffffu, acc1, off);
        }
        if (lane == 0) {
            gsh[jj * 4 + g0]     = acc0 + pre0;
            gsh[jj * 4 + g0 + 1] = acc1 + pre1;
            // prefetch next step's pregates (covers DRAM latency)
            if (t + 1 < TT) {
                pre0 = g_pre[(size_t)(t + 1) * G4 + row0];
                pre1 = g_pre[(size_t)(t + 1) * G4 + row1];
            }
        }
        __syncthreads();

        unsigned e = ebase + (unsigned)t + 1u;

        // gate math + state update + publish (threads 0..3, all in warp 0)
        if (tid < 4) {
            float gi = sigmoidf_(gsh[tid * 4 + 0]);
            float gf = sigmoidf_(gsh[tid * 4 + 1]);
            float gg = tanhfast_(gsh[tid * 4 + 2]);
            float go = sigmoidf_(gsh[tid * 4 + 3]);
            cstate   = fmaf(gf, cstate, gi * gg);
            float h  = go * tanhfast_(cstate);
            hout[(size_t)t * HH + blockIdx.x * 4 + tid] = h;
            unsigned long long pkt =
                ((unsigned long long)e << 32) |
                (unsigned long long)__float_as_uint(h);
            asm volatile(
                "st.global.relaxed.gpu.u64 [%0], %1;"
                :: "l"(&g_slots64[t & 1][blockIdx.x * 4 + tid]), "l"(pkt)
                : "memory");
        }

        if (t + 1 < TT) {
            // spin on my two h slots until the epoch tag matches
            const unsigned long long* p0 = &g_slots64[t & 1][tid];
            const unsigned long long* p1 = &g_slots64[t & 1][tid + 256];
            unsigned long long v0, v1;
            do {
                asm volatile("ld.global.relaxed.gpu.u64 %0, [%1];"
                             : "=l"(v0) : "l"(p0) : "memory");
            } while ((unsigned)(v0 >> 32) != e);
            do {
                asm volatile("ld.global.relaxed.gpu.u64 %0, [%1];"
                             : "=l"(v1) : "l"(p1) : "memory");
            } while ((unsigned)(v1 >> 32) != e);
            hsh[tid]       = __uint_as_float((unsigned)v0);
            hsh[tid + 256] = __uint_as_float((unsigned)v1);
            __syncthreads();
        }
    }
}

// ---------------- finalize: attention-weighted mean ----------------
__global__ void __launch_bounds__(1024) finalize(
    int sel, const float* __restrict__ wlin, const float* __restrict__ blin,
    float* __restrict__ out)
{
    __shared__ float wl[HH];
    __shared__ float av[TT];
    __shared__ float red[32];
    __shared__ float stats[2];

    const float* hin = sel ? g_hB : g_hA;
    int tid = threadIdx.x, w = tid >> 5, lane = tid & 31;

    for (int i = tid; i < HH; i += 1024) wl[i] = wlin[i];
    __syncthreads();
    float bl = blin[0];

    for (int r = w; r < TT; r += 32) {
        float acc = 0.0f;
#pragma unroll
        for (int k = 0; k < 16; k++)
            acc = fmaf(hin[(size_t)r * HH + lane + 32 * k], wl[lane + 32 * k], acc);
#pragma unroll
        for (int off = 16; off; off >>= 1)
            acc += __shfl_xor_sync(0xffffffffu, acc, off);
        if (lane == 0) av[r] = tanhfast_(acc + bl);
    }
    __syncthreads();

    float m = -1e30f;
    for (int i = tid; i < TT; i += 1024) m = fmaxf(m, av[i]);
#pragma unroll
    for (int off = 16; off; off >>= 1)
        m = fmaxf(m, __shfl_xor_sync(0xffffffffu, m, off));
    if (lane == 0) red[w] = m;
    __syncthreads();
    if (w == 0) {
        float mm = red[lane];
#pragma unroll
        for (int off = 16; off; off >>= 1)
            mm = fmaxf(mm, __shfl_xor_sync(0xffffffffu, mm, off));
        if (lane == 0) stats[0] = mm;
    }
    __syncthreads();
    float bmax = stats[0];

    float s = 0.0f;
    for (int i = tid; i < TT; i += 1024) {
        float e = __expf(av[i] - bmax);
        av[i] = e;
        s += e;
    }
#pragma unroll
    for (int off = 16; off; off >>= 1)
        s += __shfl_xor_sync(0xffffffffu, s, off);
    if (lane == 0) red[w] = s;
    __syncthreads();
    if (w == 0) {
        float ss = red[lane];
#pragma unroll
        for (int off = 16; off; off >>= 1)
            ss += __shfl_xor_sync(0xffffffffu, ss, off);
        if (lane == 0) stats[1] = ss;
    }
    __syncthreads();
    float inv = 1.0f / (stats[1] * (float)TT);

    int jcol = tid & (HH - 1);
    int half = tid >> 9;
    float acc = 0.0f;
    int t0 = half * (TT / 2);
    for (int t = t0; t < t0 + TT / 2; t++)
        acc = fmaf(av[t], hin[(size_t)t * HH + jcol], acc);
    __syncthreads();
    if (half == 0) wl[jcol] = acc;
    __syncthreads();
    if (half == 1) out[jcol] = (wl[jcol] + acc) * inv;
}

// ---------------- host: launch sequence (graph-capturable) ----------------
extern "C" void kernel_launch(void* const* d_in, const int* in_sizes, int n_in,
                              void* d_out, int out_size)
{
    const float* x     = (const float*)d_in[0];
    const float* w_ih0 = (const float*)d_in[1];
    const float* w_hh0 = (const float*)d_in[2];
    const float* b_ih0 = (const float*)d_in[3];
    const float* b_hh0 = (const float*)d_in[4];
    const float* w_ih  = (const float*)d_in[5];
    const float* w_hh  = (const float*)d_in[6];
    const float* b_ih  = (const float*)d_in[7];
    const float* b_hh  = (const float*)d_in[8];
    const float* w_lin = (const float*)d_in[9];
    const float* b_lin = (const float*)d_in[10];
    float* out = (float*)d_out;

    dim3 gg(G4 / 128, TT / 128);

    init_slots<<<1, 512>>>();

    // layer 0 (input dim 64)
    gemm_pregate<<<gg, 256>>>(x, 0, IN, w_ih0, b_ih0, b_hh0);
    lstm_rec<<<GRID_REC, THR_REC>>>(w_hh0, 0, 0u);   // writes g_hA

    int cur = 0;  // 0 -> g_hA holds current layer output
    for (int l = 0; l < 4; l++) {
        gemm_pregate<<<gg, 256>>>(nullptr, cur, HH,
                                  w_ih + (size_t)l * G4 * HH,
                                  b_ih + (size_t)l * G4,
                                  b_hh + (size_t)l * G4);
        lstm_rec<<<GRID_REC, THR_REC>>>(w_hh + (size_t)l * G4 * HH, cur ^ 1,
                                        (unsigned)(l + 1) * TT);
        cur ^= 1;
    }

    finalize<<<1, 1024>>>(cur, w_lin, b_lin, out);
}

// round 9
// speedup vs baseline: 2.8793x; 1.8443x over previous
#include <cuda_runtime.h>

#define TT 2048
#define IN 64
#define HH 512
#define G4 2048   /* 4*H */

// ---------------- device scratch (static allocations only) ----------------
__device__ float g_pre[TT * G4];                 // layer-0 pregates (GEMM out)
// Message board: packed {tag=t+1 (hi32) | h bits (lo32)}, one word per
// (layer, t, h-index). Cleared at the start of every launch, then written
// exactly once per launch -> race-free, no ABA, no cross-replay staleness.
__device__ unsigned long long g_msg[5 * TT * HH];   // 42 MB, L2-resident
__device__ float g_att[TT];                      // attention scores / weights

__device__ __forceinline__ float sigmoidf_(float x) {
    return 1.0f / (1.0f + __expf(-x));
}
__device__ __forceinline__ float tanhfast_(float x) {
    return 2.0f / (1.0f + __expf(-2.0f * x)) - 1.0f;
}
__device__ __forceinline__ float lstm_h_(float a0, float a1, float a2, float a3,
                                         float& c) {
    float gi = sigmoidf_(a0), gf = sigmoidf_(a1);
    float gg = tanhfast_(a2), go = sigmoidf_(a3);
    c = fmaf(gf, c, gi * gg);
    return go * tanhfast_(c);
}

__device__ __forceinline__ void pub_(unsigned long long* p, float h, unsigned tag) {
    unsigned long long pkt =
        ((unsigned long long)tag << 32) | (unsigned long long)__float_as_uint(h);
    asm volatile("st.global.relaxed.gpu.u64 [%0], %1;" :: "l"(p), "l"(pkt)
                 : "memory");
}
__device__ __forceinline__ float poll_(const unsigned long long* p, unsigned tag) {
    unsigned long long v;
    do {
        asm volatile("ld.global.relaxed.gpu.u64 %0, [%1];" : "=l"(v) : "l"(p)
                     : "memory");
    } while ((unsigned)(v >> 32) != tag);
    return __uint_as_float((unsigned)v);
}

// ---------------- clear the message board (every launch) ----------------
__global__ void __launch_bounds__(256) clear_msg() {
    size_t i = (size_t)blockIdx.x * 256 + threadIdx.x;
    g_msg[i] = 0ull;
}

// ---------------- GEMM: pre[m][n] = dot(A[m,:], B[n,:]) + b1[n] + b2[n] ----
__global__ void __launch_bounds__(256) gemm_pregate(
    const float* __restrict__ A, int K,
    const float* __restrict__ B,
    const float* __restrict__ b1, const float* __restrict__ b2)
{
    __shared__ float As[16][129];
    __shared__ float Bs[16][129];

    int tid = threadIdx.x;
    int m0 = blockIdx.y * 128;
    int n0 = blockIdx.x * 128;
    int row = tid >> 1;
    int kh  = (tid & 1) * 8;
    int tx = tid & 15, ty = tid >> 4;

    float acc[8][8];
#pragma unroll
    for (int i = 0; i < 8; i++)
#pragma unroll
        for (int j = 0; j < 8; j++) acc[i][j] = 0.0f;

    for (int kt = 0; kt < K; kt += 16) {
        float4 a0 = *(const float4*)(A + (size_t)(m0 + row) * K + kt + kh);
        float4 a1 = *(const float4*)(A + (size_t)(m0 + row) * K + kt + kh + 4);
        float4 c0 = *(const float4*)(B + (size_t)(n0 + row) * K + kt + kh);
        float4 c1 = *(const float4*)(B + (size_t)(n0 + row) * K + kt + kh + 4);
        __syncthreads();
        As[kh + 0][row] = a0.x; As[kh + 1][row] = a0.y;
        As[kh + 2][row] = a0.z; As[kh + 3][row] = a0.w;
        As[kh + 4][row] = a1.x; As[kh + 5][row] = a1.y;
        As[kh + 6][row] = a1.z; As[kh + 7][row] = a1.w;
        Bs[kh + 0][row] = c0.x; Bs[kh + 1][row] = c0.y;
        Bs[kh + 2][row] = c0.z; Bs[kh + 3][row] = c0.w;
        Bs[kh + 4][row] = c1.x; Bs[kh + 5][row] = c1.y;
        Bs[kh + 6][row] = c1.z; Bs[kh + 7][row] = c1.w;
        __syncthreads();
#pragma unroll
        for (int k = 0; k < 16; k++) {
            float a[8], b[8];
#pragma unroll
            for (int i = 0; i < 8; i++) a[i] = As[k][ty * 8 + i];
#pragma unroll
            for (int j = 0; j < 8; j++) b[j] = Bs[k][tx * 8 + j];
#pragma unroll
            for (int i = 0; i < 8; i++)
#pragma unroll
                for (int j = 0; j < 8; j++)
                    acc[i][j] = fmaf(a[i], b[j], acc[i][j]);
        }
    }

#pragma unroll
    for (int i = 0; i < 8; i++) {
        int m = m0 + ty * 8 + i;
#pragma unroll
        for (int j = 0; j < 8; j++) {
            int n = n0 + tx * 8 + j;
            g_pre[(size_t)m * G4 + n] = acc[i][j] + b1[n] + b2[n];
        }
    }
}

// ---------------- pipelined 5-layer persistent LSTM ----------------
// Grid = 144 CTAs x 512 threads, all co-resident (wave 1 on 148+ SMs,
// 1 CTA/SM due to 132KB smem -> no deadlock possible).
//   bid 0..15   : layer 0, slice owns h [32*slice, +32). hh-only (pregates
//                 from g_pre). Warp w: gates of j0 = base+2w from registers,
//                 gates of j1 = j0+1 from SMEM weights (both x hsh).
//   bid 16..143 : layer 1+ (l = 1 + (bid-16)/32), slice owns 16 h.
//                 Warp w owns all 4 gate rows of j = base+w:
//                 hh part from registers (x hsh), ih part from SMEM (x xsh).
// Exchange: g_msg words {t+1 | h}; layer l polls g_msg[l-1][t] for x and
// g_msg[l][t] to restage its own-layer h. Written once per launch.
__global__ void __launch_bounds__(512, 1) lstm_pipe(
    const float* __restrict__ whh0, const float* __restrict__ wih,
    const float* __restrict__ whh,  const float* __restrict__ bih,
    const float* __restrict__ bhh)
{
    extern __shared__ float smem[];
    float* ws  = smem;              // [64 rows][512] SMEM weights
    float* hsh = smem + 64 * 512;   // [512] own-layer h_{t-1}
    float* xsh = hsh + 512;         // [512] prev-layer h_t (layer0: pregates[128])

    int tid = threadIdx.x, w = tid >> 5, lane = tid & 31;
    int bid = blockIdx.x;
    int l, slice;
    if (bid < 16) { l = 0; slice = bid; }
    else          { l = 1 + (bid - 16) / 32; slice = (bid - 16) & 31; }
    int jb = (l == 0) ? slice * 32 : slice * 16;

    float4 wr[4][4];
    float bias0[4] = {0.f, 0.f, 0.f, 0.f};

    if (l == 0) {
        int j0 = jb + 2 * w;
#pragma unroll
        for (int g = 0; g < 4; g++)
#pragma unroll
            for (int c = 0; c < 4; c++)
                wr[g][c] = *(const float4*)&whh0[(size_t)(g * HH + j0) * HH +
                                                 c * 128 + lane * 4];
        for (int idx = tid; idx < 64 * 512; idx += 512) {
            int r = idx >> 9, col = idx & 511;
            int w_ = r >> 2, g = r & 3;
            ws[idx] = whh0[(size_t)(g * HH + jb + 2 * w_ + 1) * HH + col];
        }
    } else {
        const float* whl = whh + (size_t)(l - 1) * G4 * HH;
        const float* wil = wih + (size_t)(l - 1) * G4 * HH;
        int j = jb + w;
#pragma unroll
        for (int g = 0; g < 4; g++)
#pragma unroll
            for (int c = 0; c < 4; c++)
                wr[g][c] = *(const float4*)&whl[(size_t)(g * HH + j) * HH +
                                                c * 128 + lane * 4];
        for (int idx = tid; idx < 64 * 512; idx += 512) {
            int r = idx >> 9, col = idx & 511;
            int w_ = r >> 2, g = r & 3;
            ws[idx] = wil[(size_t)(g * HH + jb + w_) * HH + col];
        }
#pragma unroll
        for (int g = 0; g < 4; g++)
            bias0[g] = bih[(size_t)(l - 1) * G4 + g * HH + j] +
                       bhh[(size_t)(l - 1) * G4 + g * HH + j];
    }

    hsh[tid] = 0.0f;               // h_{-1} = 0
    float c0 = 0.0f, c1 = 0.0f;    // cell states (live in lane 0)
    unsigned long long* msg_own  = g_msg + (size_t)l * TT * HH;
    const unsigned long long* msg_prev =
        (l > 0) ? g_msg + (size_t)(l - 1) * TT * HH : 0;
    __syncthreads();

#pragma unroll 1
    for (int t = 0; t < TT; t++) {
        unsigned tag = (unsigned)(t + 1);

        // A) stage x (prev-layer h) or pregates
        if (l > 0) {
            xsh[tid] = poll_(msg_prev + (size_t)t * HH + tid, tag);
        } else if (tid < 128) {
            int g = tid >> 5, jo = tid & 31;
            xsh[tid] = g_pre[(size_t)t * G4 + g * HH + jb + jo];
        }
        __syncthreads();

        // B) load vectors into registers
        float4 hv[4], xv[4];
#pragma unroll
        for (int c = 0; c < 4; c++)
            hv[c] = *(float4*)&hsh[c * 128 + lane * 4];
        if (l > 0)
#pragma unroll
            for (int c = 0; c < 4; c++)
                xv[c] = *(float4*)&xsh[c * 128 + lane * 4];
        __syncthreads();   // all hsh reads done -> safe to overwrite in F

        // C) accumulate
        float acc[4], accB[4];
#pragma unroll
        for (int g = 0; g < 4; g++) { acc[g] = 0.0f; accB[g] = 0.0f; }
#pragma unroll
        for (int g = 0; g < 4; g++)
#pragma unroll
            for (int c = 0; c < 4; c++) {
                float4 a = wr[g][c], b = hv[c];
                acc[g] = fmaf(a.x, b.x, fmaf(a.y, b.y,
                          fmaf(a.z, b.z, fmaf(a.w, b.w, acc[g]))));
            }
        if (l == 0) {
#pragma unroll
            for (int g = 0; g < 4; g++)
#pragma unroll
                for (int c = 0; c < 4; c++) {
                    float4 a = *(float4*)&ws[(w * 4 + g) * 512 + c * 128 + lane * 4];
                    float4 b = hv[c];
                    accB[g] = fmaf(a.x, b.x, fmaf(a.y, b.y,
                               fmaf(a.z, b.z, fmaf(a.w, b.w, accB[g]))));
                }
        } else {
#pragma unroll
            for (int g = 0; g < 4; g++)
#pragma unroll
                for (int c = 0; c < 4; c++) {
                    float4 a = *(float4*)&ws[(w * 4 + g) * 512 + c * 128 + lane * 4];
                    float4 b = xv[c];
                    acc[g] = fmaf(a.x, b.x, fmaf(a.y, b.y,
                              fmaf(a.z, b.z, fmaf(a.w, b.w, acc[g]))));
                }
        }

        // D) warp reductions + E) gates + publish (lane 0)
        if (l == 0) {
#pragma unroll
            for (int off = 16; off; off >>= 1)
#pragma unroll
                for (int g = 0; g < 4; g++) {
                    acc[g]  += __shfl_xor_sync(0xffffffffu, acc[g],  off);
                    accB[g] += __shfl_xor_sync(0xffffffffu, accB[g], off);
                }
            if (lane == 0) {
                int j0 = jb + 2 * w;
                float h0 = lstm_h_(acc[0] + xsh[0 * 32 + 2 * w],
                                   acc[1] + xsh[1 * 32 + 2 * w],
                                   acc[2] + xsh[2 * 32 + 2 * w],
                                   acc[3] + xsh[3 * 32 + 2 * w], c0);
                float h1 = lstm_h_(accB[0] + xsh[0 * 32 + 2 * w + 1],
                                   accB[1] + xsh[1 * 32 + 2 * w + 1],
                                   accB[2] + xsh[2 * 32 + 2 * w + 1],
                                   accB[3] + xsh[3 * 32 + 2 * w + 1], c1);
                pub_(msg_own + (size_t)t * HH + j0,     h0, tag);
                pub_(msg_own + (size_t)t * HH + j0 + 1, h1, tag);
            }
        } else {
#pragma unroll
            for (int off = 16; off; off >>= 1)
#pragma unroll
                for (int g = 0; g < 4; g++)
                    acc[g] += __shfl_xor_sync(0xffffffffu, acc[g], off);
            if (lane == 0) {
                float h = lstm_h_(acc[0] + bias0[0], acc[1] + bias0[1],
                                  acc[2] + bias0[2], acc[3] + bias0[3], c0);
                pub_(msg_own + (size_t)t * HH + jb + w, h, tag);
            }
        }

        // F) restage own-layer h_t from the message board
        if (t + 1 < TT) {
            hsh[tid] = poll_(msg_own + (size_t)t * HH + tid, tag);
            __syncthreads();
        }
    }
}

// ---------------- attention finalize (3 small parallel kernels) ----------
__global__ void __launch_bounds__(256) att_e(
    const float* __restrict__ wlin, const float* __restrict__ blin)
{
    __shared__ float wl[HH];
    int tid = threadIdx.x, w = tid >> 5, lane = tid & 31;
    for (int i = tid; i < HH; i += 256) wl[i] = wlin[i];
    __syncthreads();
    float bl = blin[0];
    const unsigned long long* m4 = g_msg + (size_t)4 * TT * HH;
    for (int tt = w; tt < 128; tt += 8) {
        int t = blockIdx.x * 128 + tt;
        float acc = 0.0f;
#pragma unroll
        for (int k = 0; k < 16; k++) {
            unsigned long long v = m4[(size_t)t * HH + lane + 32 * k];
            acc = fmaf(__uint_as_float((unsigned)v), wl[lane + 32 * k], acc);
        }
#pragma unroll
        for (int off = 16; off; off >>= 1)
            acc += __shfl_xor_sync(0xffffffffu, acc, off);
        if (lane == 0) g_att[t] = tanhfast_(acc + bl);
    }
}

__global__ void __launch_bounds__(1024) att_soft() {
    __shared__ float red[32];
    __shared__ float stats[2];
    int tid = threadIdx.x, w = tid >> 5, lane = tid & 31;
    float a0 = g_att[tid], a1 = g_att[tid + 1024];
    float m = fmaxf(a0, a1);
#pragma unroll
    for (int off = 16; off; off >>= 1)
        m = fmaxf(m, __shfl_xor_sync(0xffffffffu, m, off));
    if (lane == 0) red[w] = m;
    __syncthreads();
    if (w == 0) {
        float mm = red[lane];
#pragma unroll
        for (int off = 16; off; off >>= 1)
            mm = fmaxf(mm, __shfl_xor_sync(0xffffffffu, mm, off));
        if (lane == 0) stats[0] = mm;
    }
    __syncthreads();
    float bmax = stats[0];
    float e0 = __expf(a0 - bmax), e1 = __expf(a1 - bmax);
    float s = e0 + e1;
#pragma unroll
    for (int off = 16; off; off >>= 1)
        s += __shfl_xor_sync(0xffffffffu, s, off);
    if (lane == 0) red[w] = s;
    __syncthreads();
    if (w == 0) {
        float ss = red[lane];
#pragma unroll
        for (int off = 16; off; off >>= 1)
            ss += __shfl_xor_sync(0xffffffffu, ss, off);
        if (lane == 0) stats[1] = ss;
    }
    __syncthreads();
    float inv = 1.0f / (stats[1] * (float)TT);
    g_att[tid]        = e0 * inv;
    g_att[tid + 1024] = e1 * inv;
}

__global__ void __launch_bounds__(256) att_out(float* __restrict__ out) {
    __shared__ float red[8][32];
    int tid = threadIdx.x, tx = tid & 31, ty = tid >> 5;
    int j = blockIdx.x * 32 + tx;
    const unsigned long long* m4 = g_msg + (size_t)4 * TT * HH;
    float acc = 0.0f;
    for (int t = ty; t < TT; t += 8) {
        unsigned long long v = m4[(size_t)t * HH + j];
        acc = fmaf(g_att[t], __uint_as_float((unsigned)v), acc);
    }
    red[ty][tx] = acc;
    __syncthreads();
    if (ty == 0) {
        float s = 0.0f;
#pragma unroll
        for (int r = 0; r < 8; r++) s += red[r][tx];
        out[j] = s;
    }
}

// ---------------- host: launch sequence (graph-capturable) ----------------
#define SMEM_REC ((64 * 512 + 1024) * 4)

extern "C" void kernel_launch(void* const* d_in, const int* in_sizes, int n_in,
                              void* d_out, int out_size)
{
    const float* x     = (const float*)d_in[0];
    const float* w_ih0 = (const float*)d_in[1];
    const float* w_hh0 = (const float*)d_in[2];
    const float* b_ih0 = (const float*)d_in[3];
    const float* b_hh0 = (const float*)d_in[4];
    const float* w_ih  = (const float*)d_in[5];
    const float* w_hh  = (const float*)d_in[6];
    const float* b_ih  = (const float*)d_in[7];
    const float* b_hh  = (const float*)d_in[8];
    const float* w_lin = (const float*)d_in[9];
    const float* b_lin = (const float*)d_in[10];
    float* out = (float*)d_out;

    cudaFuncSetAttribute(lstm_pipe,
                         cudaFuncAttributeMaxDynamicSharedMemorySize, SMEM_REC);

    // reset message board (fresh tags every launch / graph replay)
    clear_msg<<<(5 * TT * HH) / 256, 256>>>();

    // layer-0 input GEMM (K = 64): pre = x @ w_ih0^T + b_ih0 + b_hh0
    gemm_pregate<<<dim3(16, 16), 256>>>(x, IN, w_ih0, b_ih0, b_hh0);

    // all 5 layers, pipelined wavefront, one persistent kernel
    lstm_pipe<<<144, 512, SMEM_REC>>>(w_hh0, w_ih, w_hh, b_ih, b_hh);

    // attention readout
    att_e<<<16, 256>>>(w_lin, b_lin);
    att_soft<<<1, 1024>>>();
    att_out<<<16, 256>>>(out);
}